// round 12
// baseline (speedup 1.0000x reference)
#include <cuda_runtime.h>

// Fixed problem shape: b=16, L=256, h=256, eh=64, M=N=128 (2M=2N=256=L).
//
// Output layout (f32 elements):
//   X1      [0,          1048576)
//   X2      [1048576,    2097152)
//   E1      [2097152,    69206016)
//   E2      [69206016,   136314880)
//   A1      [136314880,  137363456)
//   A2      [137363456,  138412032)
//   mask1   [138412032,  139460608)
//   mask2   [139460608,  140509184)
//   w1      [140509184,  140513280)
//   w2      [140513280,  140517376)
//   mask_out[140517376,  141565952)
//
// Single fused kernel, 512-thread blocks, block roles interleaved
// (u32 Bresenham, one const-div per thread).
// E path = R10 layout (best measured DRAM%): 2 float4/thread, 8 threads/row
// (kb in [0,8), offsets +8) — per-warp instruction footprint = 4 rows x
// contiguous 128B.

#define SMALL_BLOCKS 3588u     // 2564 amw + 1024 X   (512-thread blocks)
#define E_BLOCKS     32768u    // 16777216 thread-slots / 512
#define TOTAL_BLOCKS 36356u    // SMALL + E

__global__ void __launch_bounds__(512) fused_kernel(
    const float4* __restrict__ E4,
    const float4* __restrict__ X4,
    const float*  __restrict__ A,
    const float4* __restrict__ mask4,
    const int*    __restrict__ mol,
    float*        __restrict__ out)
{
    unsigned bid = blockIdx.x;
    float4* out4 = reinterpret_cast<float4*>(out);

    // Bresenham interleave (u32 safe: bid*S < 1.4e8):
    // f0 = floor(bid*S/T); block is small iff rem >= T - S (= 2^15).
    unsigned num = bid * SMALL_BLOCKS;
    unsigned f0  = num / TOTAL_BLOCKS;
    unsigned rem = num - f0 * TOTAL_BLOCKS;
    bool is_small = (rem >= 32768u);             // T - S = 2^15

    if (!is_small) {
        // ------------------------------------------------------------------
        // E1 / E2 gather: 2 float4 per thread (kb, kb+8).
        // g in [0, 16777216). row r = g>>3 (bits [20]=t [19:16]=bi
        // [15:8]=i [7:0]=j), kb = g&7.
        // ------------------------------------------------------------------
        unsigned g = (bid - f0) * 512u + threadIdx.x;
        unsigned r = g >> 3;
        int kb = g & 7;
        int t  = r >> 20;
        int bi = (r >> 16) & 15;
        int i  = (r >> 8)  & 255;
        int j  = r & 255;

        int l0 = __ldg(&mol[bi * 2]);
        int l  = t ? __ldg(&mol[bi * 2 + 1]) : l0;

        bool fi = i < l;
        bool fj = j < l;
        bool si = !fi && (i < 2 * l);
        bool sj = !fj && (j < 2 * l);
        bool valid = (fi && fj) || (si && sj);

        unsigned obase = t ? 17301504u : 524288u;
        unsigned d = obase + ((r & 0xFFFFFu) << 4) + (unsigned)kb;

        if (valid) {
            int ri = fi ? i : i - l;
            int rj = fj ? j : j - l;
            if (t) {
                ri = min(ri + l0, 255);
                rj = min(rj + l0, 255);
            }
            unsigned s = (unsigned)((((bi << 8) + ri) << 8) + rj) * 16u + (unsigned)kb;
            float4 v0 = __ldg(&E4[s]);
            float4 v1 = __ldg(&E4[s + 8]);
            out4[d]     = v0;
            out4[d + 8] = v1;
        } else {
            float4 z = make_float4(0.f, 0.f, 0.f, 0.f);
            out4[d]     = z;
            out4[d + 8] = z;
        }
        return;
    }

    unsigned sb = f0;                           // small block index in [0, 3588)

    if (sb >= 2564u) {
        // ------------------------------------------------------------------
        // X1 / X2: idx bits [18]=t [17:14]=bi [13:6]=p [5:0]=k4
        // ------------------------------------------------------------------
        unsigned idx = (sb - 2564u) * 512u + threadIdx.x;
        int t  = idx >> 18;
        int bi = (idx >> 14) & 15;
        int p  = (idx >> 6)  & 255;
        int k4 = idx & 63;

        int l = __ldg(&mol[bi * 2 + t]);

        float4 v = make_float4(0.f, 0.f, 0.f, 0.f);
        if (p < 2 * l) {
            int sp = (p < l) ? p : p - l;
            v = __ldg(&X4[(unsigned)(((bi << 8) + sp) << 6) + (unsigned)k4]);
        }
        out4[(t ? 262144u : 0u) + (idx & 0x0003FFFFu)] = v;
        return;
    }

    // ----------------------------------------------------------------------
    // amw: A1/A2/mask1/mask2 [0,1048576), mask_out [1048576,1310720),
    //      w zeros [1310720,1312768)
    // ----------------------------------------------------------------------
    unsigned idx = sb * 512u + threadIdx.x;

    if (idx < 1048576u) {
        int t2 = idx >> 18;          // 0:A1 1:A2 2:mask1 3:mask2
        int bi = (idx >> 14) & 15;
        int i  = (idx >> 6)  & 255;
        int j0 = (idx & 63) * 4;
        int tt = t2 & 1;

        int l0 = __ldg(&mol[bi * 2]);
        int l  = tt ? __ldg(&mol[bi * 2 + 1]) : l0;

        bool fi = i < l;
        bool si = !fi && (i < 2 * l);
        int ri = fi ? i : i - l;
        if (tt) ri = min(ri + l0, 255);

        float4 v;
        float* vv = &v.x;
        #pragma unroll
        for (int q = 0; q < 4; q++) {
            int j = j0 + q;
            bool fj = j < l;
            bool sj = !fj && (j < 2 * l);
            if (t2 < 2) {
                float a = 0.f;
                if ((fi && fj) || (si && sj)) {
                    int rj = fj ? j : j - l;
                    if (tt) rj = min(rj + l0, 255);
                    a = __ldg(&A[(unsigned)(bi << 16) + (unsigned)(ri << 8) + (unsigned)rj]);
                }
                vv[q] = a;
            } else {
                bool bad = (fi && sj) || (si && fj);
                vv[q] = bad ? 0.f : 1.f;
            }
        }
        out4[34078720u + (unsigned)t2 * 262144u + (idx & 0x0003FFFFu)] = v;
    }
    else if (idx < 1310720u) {
        unsigned m = idx - 1048576u;
        int bi = (m >> 14) & 15;
        int i  = (m >> 6)  & 255;
        int j0 = (m & 63) * 4;

        int l0 = __ldg(&mol[bi * 2]);
        int l1 = __ldg(&mol[bi * 2 + 1]);
        int lsum = l0 + l1;

        bool li = i < l0;
        bool mi = !li && (i < lsum);

        float4 mb = __ldg(&mask4[((unsigned)(bi << 16) + (unsigned)(i << 8) + (unsigned)j0) >> 2]);
        const float* mbp = &mb.x;

        float4 v;
        float* vv = &v.x;
        #pragma unroll
        for (int q = 0; q < 4; q++) {
            int j = j0 + q;
            bool lj = j < l0;
            bool mj = !lj && (j < lsum);
            float r;
            if (li == lj)                        r = 1.f;
            else if ((li && mj) || (mi && lj))   r = 0.f;
            else r = (mbp[q] != 0.f) ? 1.f : 0.f;
            vv[q] = r;
        }
        out4[35129344u + m] = v;
    }
    else if (idx < 1312768u) {
        out4[35127296u + (idx - 1310720u)] = make_float4(0.f, 0.f, 0.f, 0.f);
    }
}

extern "C" void kernel_launch(void* const* d_in, const int* in_sizes, int n_in,
                              void* d_out, int out_size)
{
    const float4* X    = (const float4*)d_in[0];
    const float4* E    = (const float4*)d_in[1];
    const float*  A    = (const float*)d_in[2];
    // d_in[3] = w (unused: w1/w2 are zeros)
    const float4* mask = (const float4*)d_in[4];
    const int*    mol  = (const int*)d_in[5];
    float*        out  = (float*)d_out;

    fused_kernel<<<TOTAL_BLOCKS, 512>>>(E, X, A, mask, mol, out);
}

// round 13
// speedup vs baseline: 1.0114x; 1.0114x over previous
#include <cuda_runtime.h>

// FINAL KERNEL (= Round-11 best, 102.0 us, DRAM-floor-bound).
//
// Fixed problem shape: b=16, L=256, h=256, eh=64, M=N=128 (2M=2N=256=L).
//
// Output layout (f32 elements):
//   X1      [0,          1048576)
//   X2      [1048576,    2097152)
//   E1      [2097152,    69206016)
//   E2      [69206016,   136314880)
//   A1      [136314880,  137363456)
//   A2      [137363456,  138412032)
//   mask1   [138412032,  139460608)
//   mask2   [139460608,  140509184)
//   w1      [140509184,  140513280)
//   w2      [140513280,  140517376)
//   mask_out[140517376,  141565952)
//
// Single fused kernel, block roles interleaved (u32 Bresenham, one const-div).
// E path: ONE 256-bit load + ONE 256-bit store per thread (sm_100+ v8.f32),
// 8 threads/row; per-warp instruction footprint = contiguous 8KB.
//
// Perf model (measured over 8 rounds): 566 MB compulsory writes + ~39 MB DRAM
// reads (gather reads L2-absorbed) at ~6.1 TB/s => ~98.5 us kernel; all SM
// pipes <40% busy. Write-bandwidth floor; converged.

#define SMALL_BLOCKS 7176u     // 5128 amw + 2048 X
#define E_BLOCKS     65536u    // 16777216 f8 / 256 threads
#define TOTAL_BLOCKS 72712u    // SMALL + E

__device__ __forceinline__ void ldg256(const float* p, float* v) {
    asm volatile("ld.global.nc.v8.f32 {%0,%1,%2,%3,%4,%5,%6,%7}, [%8];"
        : "=f"(v[0]), "=f"(v[1]), "=f"(v[2]), "=f"(v[3]),
          "=f"(v[4]), "=f"(v[5]), "=f"(v[6]), "=f"(v[7])
        : "l"(p));
}

__device__ __forceinline__ void stg256(float* p, const float* v) {
    asm volatile("st.global.v8.f32 [%0], {%1,%2,%3,%4,%5,%6,%7,%8};"
        :: "l"(p),
           "f"(v[0]), "f"(v[1]), "f"(v[2]), "f"(v[3]),
           "f"(v[4]), "f"(v[5]), "f"(v[6]), "f"(v[7])
        : "memory");
}

__global__ void __launch_bounds__(256) fused_kernel(
    const float*  __restrict__ E,
    const float4* __restrict__ X4,
    const float*  __restrict__ A,
    const float4* __restrict__ mask4,
    const int*    __restrict__ mol,
    float*        __restrict__ out)
{
    unsigned bid = blockIdx.x;
    float4* out4 = reinterpret_cast<float4*>(out);

    // Bresenham interleave (u32 safe: bid*S < 5.3e8):
    // f0 = floor(bid*S/T); block is small iff rem >= T - S (= 2^16).
    unsigned num = bid * SMALL_BLOCKS;
    unsigned f0  = num / TOTAL_BLOCKS;
    unsigned rem = num - f0 * TOTAL_BLOCKS;
    bool is_small = (rem >= 65536u);             // T - S = 2^16

    if (!is_small) {
        // ------------------------------------------------------------------
        // E1 / E2 gather: one f8 (32B) per thread.
        // g in [0, 16777216). row r = g>>3 (bits [20]=t [19:16]=bi
        // [15:8]=i [7:0]=j), kb = g&7 (f8 index within 256B row).
        // ------------------------------------------------------------------
        unsigned g = (bid - f0) * 256u + threadIdx.x;
        unsigned r = g >> 3;
        int kb = g & 7;
        int t  = r >> 20;
        int bi = (r >> 16) & 15;
        int i  = (r >> 8)  & 255;
        int j  = r & 255;

        int l0 = __ldg(&mol[bi * 2]);
        int l  = t ? __ldg(&mol[bi * 2 + 1]) : l0;

        bool fi = i < l;
        bool fj = j < l;
        bool si = !fi && (i < 2 * l);
        bool sj = !fj && (j < 2 * l);
        bool valid = (fi && fj) || (si && sj);

        // destination float offset: base + row*64 + kb*8
        unsigned obase = t ? 69206016u : 2097152u;   // E2 / E1 base in floats
        float* dst = out + obase + ((r & 0xFFFFFu) << 6) + ((unsigned)kb << 3);

        float v[8];
        if (valid) {
            int ri = fi ? i : i - l;
            int rj = fj ? j : j - l;
            if (t) {
                ri = min(ri + l0, 255);
                rj = min(rj + l0, 255);
            }
            const float* src = E + (unsigned)((((bi << 8) + ri) << 8) + rj) * 64u
                                 + ((unsigned)kb << 3);
            ldg256(src, v);
        } else {
            #pragma unroll
            for (int q = 0; q < 8; q++) v[q] = 0.f;
        }
        stg256(dst, v);
        return;
    }

    unsigned sb = f0;                           // small block index in [0, 7176)

    if (sb >= 5128u) {
        // ------------------------------------------------------------------
        // X1 / X2: idx bits [18]=t [17:14]=bi [13:6]=p [5:0]=k4
        // ------------------------------------------------------------------
        unsigned idx = (sb - 5128u) * 256u + threadIdx.x;
        int t  = idx >> 18;
        int bi = (idx >> 14) & 15;
        int p  = (idx >> 6)  & 255;
        int k4 = idx & 63;

        int l = __ldg(&mol[bi * 2 + t]);

        float4 v = make_float4(0.f, 0.f, 0.f, 0.f);
        if (p < 2 * l) {
            int sp = (p < l) ? p : p - l;
            v = __ldg(&X4[(unsigned)(((bi << 8) + sp) << 6) + (unsigned)k4]);
        }
        out4[(t ? 262144u : 0u) + (idx & 0x0003FFFFu)] = v;
        return;
    }

    // ----------------------------------------------------------------------
    // amw: A1/A2/mask1/mask2 [0,1048576), mask_out [1048576,1310720),
    //      w zeros [1310720,1312768)
    // ----------------------------------------------------------------------
    unsigned idx = sb * 256u + threadIdx.x;

    if (idx < 1048576u) {
        int t2 = idx >> 18;          // 0:A1 1:A2 2:mask1 3:mask2
        int bi = (idx >> 14) & 15;
        int i  = (idx >> 6)  & 255;
        int j0 = (idx & 63) * 4;
        int tt = t2 & 1;

        int l0 = __ldg(&mol[bi * 2]);
        int l  = tt ? __ldg(&mol[bi * 2 + 1]) : l0;

        bool fi = i < l;
        bool si = !fi && (i < 2 * l);
        int ri = fi ? i : i - l;
        if (tt) ri = min(ri + l0, 255);

        float4 v;
        float* vv = &v.x;
        #pragma unroll
        for (int q = 0; q < 4; q++) {
            int j = j0 + q;
            bool fj = j < l;
            bool sj = !fj && (j < 2 * l);
            if (t2 < 2) {
                float a = 0.f;
                if ((fi && fj) || (si && sj)) {
                    int rj = fj ? j : j - l;
                    if (tt) rj = min(rj + l0, 255);
                    a = __ldg(&A[(unsigned)(bi << 16) + (unsigned)(ri << 8) + (unsigned)rj]);
                }
                vv[q] = a;
            } else {
                bool bad = (fi && sj) || (si && fj);
                vv[q] = bad ? 0.f : 1.f;
            }
        }
        out4[34078720u + (unsigned)t2 * 262144u + (idx & 0x0003FFFFu)] = v;
    }
    else if (idx < 1310720u) {
        unsigned m = idx - 1048576u;
        int bi = (m >> 14) & 15;
        int i  = (m >> 6)  & 255;
        int j0 = (m & 63) * 4;

        int l0 = __ldg(&mol[bi * 2]);
        int l1 = __ldg(&mol[bi * 2 + 1]);
        int lsum = l0 + l1;

        bool li = i < l0;
        bool mi = !li && (i < lsum);

        float4 mb = __ldg(&mask4[((unsigned)(bi << 16) + (unsigned)(i << 8) + (unsigned)j0) >> 2]);
        const float* mbp = &mb.x;

        float4 v;
        float* vv = &v.x;
        #pragma unroll
        for (int q = 0; q < 4; q++) {
            int j = j0 + q;
            bool lj = j < l0;
            bool mj = !lj && (j < lsum);
            float r;
            if (li == lj)                        r = 1.f;
            else if ((li && mj) || (mi && lj))   r = 0.f;
            else r = (mbp[q] != 0.f) ? 1.f : 0.f;
            vv[q] = r;
        }
        out4[35129344u + m] = v;
    }
    else if (idx < 1312768u) {
        out4[35127296u + (idx - 1310720u)] = make_float4(0.f, 0.f, 0.f, 0.f);
    }
}

extern "C" void kernel_launch(void* const* d_in, const int* in_sizes, int n_in,
                              void* d_out, int out_size)
{
    const float4* X    = (const float4*)d_in[0];
    const float*  E    = (const float*)d_in[1];
    const float*  A    = (const float*)d_in[2];
    // d_in[3] = w (unused: w1/w2 are zeros)
    const float4* mask = (const float4*)d_in[4];
    const int*    mol  = (const int*)d_in[5];
    float*        out  = (float*)d_out;

    fused_kernel<<<TOTAL_BLOCKS, 256>>>(E, X, A, mask, mol, out);
}

// round 14
// speedup vs baseline: 1.0171x; 1.0057x over previous
#include <cuda_runtime.h>

// FINAL KERNEL (best measured: 101.4 us, DRAM-floor-bound; converged).
//
// Fixed problem shape: b=16, L=256, h=256, eh=64, M=N=128 (2M=2N=256=L).
//
// Output layout (f32 elements):
//   X1      [0,          1048576)
//   X2      [1048576,    2097152)
//   E1      [2097152,    69206016)
//   E2      [69206016,   136314880)
//   A1      [136314880,  137363456)
//   A2      [137363456,  138412032)
//   mask1   [138412032,  139460608)
//   mask2   [139460608,  140509184)
//   w1      [140509184,  140513280)
//   w2      [140513280,  140517376)
//   mask_out[140517376,  141565952)
//
// Single fused kernel, block roles interleaved (u32 Bresenham, one const-div).
// E path: ONE 256-bit load + ONE 256-bit store per thread (sm_100+ v8.f32),
// 8 threads/row; per-warp instruction footprint = contiguous 8KB.
//
// Perf model (measured over 12 rounds): 566 MB compulsory writes + ~39 MB
// DRAM reads (gather reads L2-absorbed) at ~6.16 TB/s => ~98 us kernel; all
// SM pipes <40% busy; remaining DRAM idle = R/W turnaround on a 93%-write
// stream. Write-bandwidth floor; session converged.

#define SMALL_BLOCKS 7176u     // 5128 amw + 2048 X
#define E_BLOCKS     65536u    // 16777216 f8 / 256 threads
#define TOTAL_BLOCKS 72712u    // SMALL + E

__device__ __forceinline__ void ldg256(const float* p, float* v) {
    asm volatile("ld.global.nc.v8.f32 {%0,%1,%2,%3,%4,%5,%6,%7}, [%8];"
        : "=f"(v[0]), "=f"(v[1]), "=f"(v[2]), "=f"(v[3]),
          "=f"(v[4]), "=f"(v[5]), "=f"(v[6]), "=f"(v[7])
        : "l"(p));
}

__device__ __forceinline__ void stg256(float* p, const float* v) {
    asm volatile("st.global.v8.f32 [%0], {%1,%2,%3,%4,%5,%6,%7,%8};"
        :: "l"(p),
           "f"(v[0]), "f"(v[1]), "f"(v[2]), "f"(v[3]),
           "f"(v[4]), "f"(v[5]), "f"(v[6]), "f"(v[7])
        : "memory");
}

__global__ void __launch_bounds__(256) fused_kernel(
    const float*  __restrict__ E,
    const float4* __restrict__ X4,
    const float*  __restrict__ A,
    const float4* __restrict__ mask4,
    const int*    __restrict__ mol,
    float*        __restrict__ out)
{
    unsigned bid = blockIdx.x;
    float4* out4 = reinterpret_cast<float4*>(out);

    // Bresenham interleave (u32 safe: bid*S < 5.3e8):
    // f0 = floor(bid*S/T); block is small iff rem >= T - S (= 2^16).
    unsigned num = bid * SMALL_BLOCKS;
    unsigned f0  = num / TOTAL_BLOCKS;
    unsigned rem = num - f0 * TOTAL_BLOCKS;
    bool is_small = (rem >= 65536u);             // T - S = 2^16

    if (!is_small) {
        // ------------------------------------------------------------------
        // E1 / E2 gather: one f8 (32B) per thread.
        // g in [0, 16777216). row r = g>>3 (bits [20]=t [19:16]=bi
        // [15:8]=i [7:0]=j), kb = g&7 (f8 index within 256B row).
        // ------------------------------------------------------------------
        unsigned g = (bid - f0) * 256u + threadIdx.x;
        unsigned r = g >> 3;
        int kb = g & 7;
        int t  = r >> 20;
        int bi = (r >> 16) & 15;
        int i  = (r >> 8)  & 255;
        int j  = r & 255;

        int l0 = __ldg(&mol[bi * 2]);
        int l  = t ? __ldg(&mol[bi * 2 + 1]) : l0;

        bool fi = i < l;
        bool fj = j < l;
        bool si = !fi && (i < 2 * l);
        bool sj = !fj && (j < 2 * l);
        bool valid = (fi && fj) || (si && sj);

        // destination float offset: base + row*64 + kb*8
        unsigned obase = t ? 69206016u : 2097152u;   // E2 / E1 base in floats
        float* dst = out + obase + ((r & 0xFFFFFu) << 6) + ((unsigned)kb << 3);

        float v[8];
        if (valid) {
            int ri = fi ? i : i - l;
            int rj = fj ? j : j - l;
            if (t) {
                ri = min(ri + l0, 255);
                rj = min(rj + l0, 255);
            }
            const float* src = E + (unsigned)((((bi << 8) + ri) << 8) + rj) * 64u
                                 + ((unsigned)kb << 3);
            ldg256(src, v);
        } else {
            #pragma unroll
            for (int q = 0; q < 8; q++) v[q] = 0.f;
        }
        stg256(dst, v);
        return;
    }

    unsigned sb = f0;                           // small block index in [0, 7176)

    if (sb >= 5128u) {
        // ------------------------------------------------------------------
        // X1 / X2: idx bits [18]=t [17:14]=bi [13:6]=p [5:0]=k4
        // ------------------------------------------------------------------
        unsigned idx = (sb - 5128u) * 256u + threadIdx.x;
        int t  = idx >> 18;
        int bi = (idx >> 14) & 15;
        int p  = (idx >> 6)  & 255;
        int k4 = idx & 63;

        int l = __ldg(&mol[bi * 2 + t]);

        float4 v = make_float4(0.f, 0.f, 0.f, 0.f);
        if (p < 2 * l) {
            int sp = (p < l) ? p : p - l;
            v = __ldg(&X4[(unsigned)(((bi << 8) + sp) << 6) + (unsigned)k4]);
        }
        out4[(t ? 262144u : 0u) + (idx & 0x0003FFFFu)] = v;
        return;
    }

    // ----------------------------------------------------------------------
    // amw: A1/A2/mask1/mask2 [0,1048576), mask_out [1048576,1310720),
    //      w zeros [1310720,1312768)
    // ----------------------------------------------------------------------
    unsigned idx = sb * 256u + threadIdx.x;

    if (idx < 1048576u) {
        int t2 = idx >> 18;          // 0:A1 1:A2 2:mask1 3:mask2
        int bi = (idx >> 14) & 15;
        int i  = (idx >> 6)  & 255;
        int j0 = (idx & 63) * 4;
        int tt = t2 & 1;

        int l0 = __ldg(&mol[bi * 2]);
        int l  = tt ? __ldg(&mol[bi * 2 + 1]) : l0;

        bool fi = i < l;
        bool si = !fi && (i < 2 * l);
        int ri = fi ? i : i - l;
        if (tt) ri = min(ri + l0, 255);

        float4 v;
        float* vv = &v.x;
        #pragma unroll
        for (int q = 0; q < 4; q++) {
            int j = j0 + q;
            bool fj = j < l;
            bool sj = !fj && (j < 2 * l);
            if (t2 < 2) {
                float a = 0.f;
                if ((fi && fj) || (si && sj)) {
                    int rj = fj ? j : j - l;
                    if (tt) rj = min(rj + l0, 255);
                    a = __ldg(&A[(unsigned)(bi << 16) + (unsigned)(ri << 8) + (unsigned)rj]);
                }
                vv[q] = a;
            } else {
                bool bad = (fi && sj) || (si && fj);
                vv[q] = bad ? 0.f : 1.f;
            }
        }
        out4[34078720u + (unsigned)t2 * 262144u + (idx & 0x0003FFFFu)] = v;
    }
    else if (idx < 1310720u) {
        unsigned m = idx - 1048576u;
        int bi = (m >> 14) & 15;
        int i  = (m >> 6)  & 255;
        int j0 = (m & 63) * 4;

        int l0 = __ldg(&mol[bi * 2]);
        int l1 = __ldg(&mol[bi * 2 + 1]);
        int lsum = l0 + l1;

        bool li = i < l0;
        bool mi = !li && (i < lsum);

        float4 mb = __ldg(&mask4[((unsigned)(bi << 16) + (unsigned)(i << 8) + (unsigned)j0) >> 2]);
        const float* mbp = &mb.x;

        float4 v;
        float* vv = &v.x;
        #pragma unroll
        for (int q = 0; q < 4; q++) {
            int j = j0 + q;
            bool lj = j < l0;
            bool mj = !lj && (j < lsum);
            float r;
            if (li == lj)                        r = 1.f;
            else if ((li && mj) || (mi && lj))   r = 0.f;
            else r = (mbp[q] != 0.f) ? 1.f : 0.f;
            vv[q] = r;
        }
        out4[35129344u + m] = v;
    }
    else if (idx < 1312768u) {
        out4[35127296u + (idx - 1310720u)] = make_float4(0.f, 0.f, 0.f, 0.f);
    }
}

extern "C" void kernel_launch(void* const* d_in, const int* in_sizes, int n_in,
                              void* d_out, int out_size)
{
    const float4* X    = (const float4*)d_in[0];
    const float*  E    = (const float*)d_in[1];
    const float*  A    = (const float*)d_in[2];
    // d_in[3] = w (unused: w1/w2 are zeros)
    const float4* mask = (const float4*)d_in[4];
    const int*    mol  = (const int*)d_in[5];
    float*        out  = (float*)d_out;

    fused_kernel<<<TOTAL_BLOCKS, 256>>>(E, X, A, mask, mol, out);
}